// round 11
// baseline (speedup 1.0000x reference)
#include <cuda_runtime.h>
#include <cuda_fp16.h>
#include <cstdint>

#define BATCH   4096
#define HN      16
#define N1      192
#define DIM     256
#define TWO_DIM 512
#define EPS     1e-5f
#define GB      4            // batches per CTA
#define THREADS 512

// ---- smem layout (bytes) ----
#define OFF_XHI  0           // xhi fp16 64x1040 = 66560 -> later o f32 (64x260x4)
#define OFF_H    66560       // h fp16 64x528 = 33792
#define OFF_IDX  100352      // 768 ints
#define OFF_B1   103424      // 256 f32
#define OFF_B2   104448      // 512 f32
#define OFF_LNG  106496      // 512 f32
#define OFF_LNB  108544      // 512 f32
#define SMEM_BYTES 110592

#define XSTRIDE_W 260        // u32 words per xhi row (256 data + 4 pad; ≡4 mod 32)
#define XSTRIDE_B 1040
#define HSTRIDE_W 132        // u32 words per h row (128 data + 4 pad)
#define HSTRIDE_B 528
#define OSTRIDE_W 260        // f32 words per o row (256 data + 4 pad)

// Pre-swizzled fp16 weights in B-fragment order. 256KB each.
__device__ __align__(16) __half g_W1s[131072];
__device__ __align__(16) __half g_W2s[131072];

__device__ __forceinline__ uint32_t smem_u32(const void* p) {
    return (uint32_t)__cvta_generic_to_shared(p);
}

__device__ __forceinline__ void ldsm4(uint32_t (&r)[4], uint32_t addr) {
    asm volatile("ldmatrix.sync.aligned.m8n8.x4.shared.b16 {%0,%1,%2,%3}, [%4];"
                 : "=r"(r[0]), "=r"(r[1]), "=r"(r[2]), "=r"(r[3]) : "r"(addr));
}

__device__ __forceinline__ void mma16816(float (&c)[4], const uint32_t (&a)[4],
                                         uint32_t b0, uint32_t b1) {
    asm volatile("mma.sync.aligned.m16n8k16.row.col.f32.f16.f16.f32 "
                 "{%0,%1,%2,%3}, {%4,%5,%6,%7}, {%8,%9}, {%0,%1,%2,%3};"
                 : "+f"(c[0]), "+f"(c[1]), "+f"(c[2]), "+f"(c[3])
                 : "r"(a[0]), "r"(a[1]), "r"(a[2]), "r"(a[3]), "r"(b0), "r"(b1));
}

__device__ __forceinline__ float sigmoidf(float x) {
    return 1.0f / (1.0f + __expf(-x));
}

// Swizzle both W1[256][512] and W2[512][256] into per-tile B-fragment order (fp16).
__global__ void prep_weights(const float* __restrict__ W1,
                             const float* __restrict__ W2) {
    int t = blockIdx.x * blockDim.x + threadIdx.x;   // [0, 131072)
    const float* W;
    __half2* dst;
    int kpairs, K;
    if (t < 65536) { W = W1; dst = (__half2*)g_W1s; kpairs = 16; K = 512; }
    else           { W = W2; dst = (__half2*)g_W2s; kpairs = 8;  K = 256; t -= 65536; }
    int j    = t & 3;
    int lane = (t >> 2) & 31;
    int rest = t >> 7;
    int kp    = rest % kpairs;
    int ntile = rest / kpairs;
    int n = ntile * 8 + (lane >> 2);
    int k = kp * 32 + (j >> 1) * 16 + (j & 1) * 8 + 2 * (lane & 3);
    dst[(((ntile * kpairs + kp) * 32 + lane) << 2) + j] =
        __floats2half2_rn(W[n * K + k], W[n * K + k + 1]);
}

__global__ __launch_bounds__(THREADS, 2)
void mlp_two_main(const float* __restrict__ rgb, const float* __restrict__ tir,
                  const int* __restrict__ gidx, const float* __restrict__ ln_g,
                  const float* __restrict__ ln_b, const float* __restrict__ b1,
                  const float* __restrict__ b2, float* __restrict__ out)
{
    extern __shared__ char smem[];
    uint32_t* xhi   = (uint32_t*)(smem + OFF_XHI);
    float*    osm   = (float*)(smem + OFF_XHI);
    uint32_t* hsm   = (uint32_t*)(smem + OFF_H);
    int*      idx_s = (int*)(smem + OFF_IDX);
    float*    b1s   = (float*)(smem + OFF_B1);
    float*    b2s   = (float*)(smem + OFF_B2);
    float*    lngs  = (float*)(smem + OFF_LNG);
    float*    lnbs  = (float*)(smem + OFF_LNB);

    const int tid  = threadIdx.x;
    const int lane = tid & 31;
    const int wid  = tid >> 5;

    // ---- preload idx / biases / LN params ----
    if (tid < 256) b1s[tid] = b1[tid];
    b2s[tid]  = b2[tid];
    lngs[tid] = ln_g[tid];
    lnbs[tid] = ln_b[tid];
    idx_s[tid] = gidx[blockIdx.x * (GB * N1) + tid];
    if (tid < GB * N1 - THREADS)
        idx_s[THREADS + tid] = gidx[blockIdx.x * (GB * N1) + THREADS + tid];
    __syncthreads();

    const float* rgb_cta = rgb + (size_t)blockIdx.x * (GB * HN * N1);
    const float* tir_cta = tir + (size_t)blockIdx.x * (GB * HN * N1);

    // ======== fused scatter + LayerNorm, direct fp16 write (4 rows/warp) ========
    #pragma unroll 1
    for (int rr = 0; rr < 4; rr++) {
        const int r = wid * 4 + rr;            // 0..63
        const int g = r >> 4;                  // local batch
        const float* rowr = rgb_cta + r * N1;
        const float* rowt = tir_cta + r * N1;
        float vr[6], vt[6];
        float s = 0.f, sq = 0.f;
        #pragma unroll
        for (int i = 0; i < 6; i++) {
            vr[i] = rowr[lane + 32 * i];
            vt[i] = rowt[lane + 32 * i];
            s  += vr[i] + vt[i];
            sq += vr[i] * vr[i] + vt[i] * vt[i];
        }
        #pragma unroll
        for (int o = 16; o > 0; o >>= 1) {
            s  += __shfl_xor_sync(~0u, s,  o);
            sq += __shfl_xor_sync(~0u, sq, o);
        }
        const float mu = s * (1.f / 512.f);
        const float rs = rsqrtf(sq * (1.f / 512.f) - mu * mu + EPS);
        const float nmr = -mu * rs;

        // fill whole row with zero-position LN value: b[k] - mu*rs*g[k]
        uint32_t* xrow = xhi + r * XSTRIDE_W;
        #pragma unroll
        for (int i = 0; i < 8; i++) {
            int kw = lane + 32 * i;            // word 0..255
            float2 g2 = *(const float2*)(lngs + 2 * kw);
            float2 bb = *(const float2*)(lnbs + 2 * kw);
            __half2 hv = __floats2half2_rn(fmaf(nmr, g2.x, bb.x),
                                           fmaf(nmr, g2.y, bb.y));
            xrow[kw] = *(uint32_t*)&hv;
        }
        __syncwarp();
        // scatter the 192 selected columns (rgb -> c, tir -> 256+c)
        __half* xrow_h = (__half*)xrow;
        #pragma unroll
        for (int i = 0; i < 6; i++) {
            int j = lane + 32 * i;
            int c = idx_s[g * N1 + j];
            float xv = (vr[i] - mu) * rs * lngs[c]       + lnbs[c];
            float tv = (vt[i] - mu) * rs * lngs[DIM + c] + lnbs[DIM + c];
            xrow_h[c]       = __float2half_rn(xv);
            xrow_h[DIM + c] = __float2half_rn(tv);
        }
    }
    __syncthreads();

    // ---- warp tile geometry: 2 mtiles (32 rows) x 8 ngroups (32 cols) ----
    const int mt = wid & 1, ng = wid >> 1;
    const int m0 = mt * 32;
    const int q  = lane >> 3, qr = lane & 7;
    const int arow16 = (q & 1) * 8 + qr;       // row within 16-block
    const uint32_t acol = (q >> 1) * 16;       // bytes
    const uint32_t xa0 = smem_u32(smem + OFF_XHI) + (m0 + arow16)      * XSTRIDE_B + acol;
    const uint32_t xa1 = smem_u32(smem + OFF_XHI) + (m0 + 16 + arow16) * XSTRIDE_B + acol;

    // ======== GEMM1: [64x512] @ W1^T -> h [64x256] fp16 ========
    {
        float acc[2][4][4];
        #pragma unroll
        for (int rb = 0; rb < 2; rb++)
            #pragma unroll
            for (int nt = 0; nt < 4; nt++)
                { acc[rb][nt][0]=0.f; acc[rb][nt][1]=0.f; acc[rb][nt][2]=0.f; acc[rb][nt][3]=0.f; }

        #pragma unroll 2
        for (int kp = 0; kp < 16; kp++) {
            uint32_t a00[4], a01[4], a10[4], a11[4];
            ldsm4(a00, xa0 + kp * 64);
            ldsm4(a01, xa0 + kp * 64 + 32);
            ldsm4(a10, xa1 + kp * 64);
            ldsm4(a11, xa1 + kp * 64 + 32);
            #pragma unroll
            for (int nt = 0; nt < 4; nt++) {
                int ntile = ng * 4 + nt;
                uint4 bh = __ldg(((const uint4*)g_W1s) + (ntile * 16 + kp) * 32 + lane);
                mma16816(acc[0][nt], a00, bh.x, bh.y);
                mma16816(acc[0][nt], a01, bh.z, bh.w);
                mma16816(acc[1][nt], a10, bh.x, bh.y);
                mma16816(acc[1][nt], a11, bh.z, bh.w);
            }
        }
        // epilogue: +bias, relu, fp16 round, store h
        #pragma unroll
        for (int rb = 0; rb < 2; rb++) {
            int r0 = m0 + rb * 16 + (lane >> 2), r1 = r0 + 8;
            #pragma unroll
            for (int nt = 0; nt < 4; nt++) {
                int cn = ng * 32 + nt * 8 + 2 * (lane & 3);
                int cw = cn >> 1;
                float2 bb = *(const float2*)(b1s + cn);
                __half2 h0 = __floats2half2_rn(fmaxf(acc[rb][nt][0] + bb.x, 0.f),
                                               fmaxf(acc[rb][nt][1] + bb.y, 0.f));
                __half2 h1 = __floats2half2_rn(fmaxf(acc[rb][nt][2] + bb.x, 0.f),
                                               fmaxf(acc[rb][nt][3] + bb.y, 0.f));
                hsm[r0 * HSTRIDE_W + cw] = *(uint32_t*)&h0;
                hsm[r1 * HSTRIDE_W + cw] = *(uint32_t*)&h1;
            }
        }
    }
    __syncthreads();

    // ======== GEMM2 (two 256-col halves) + sigmoid + gather ========
    const uint32_t ha0 = smem_u32(smem + OFF_H) + (m0 + arow16)      * HSTRIDE_B + acol;
    const uint32_t ha1 = smem_u32(smem + OFF_H) + (m0 + 16 + arow16) * HSTRIDE_B + acol;
    const size_t out_base = (size_t)blockIdx.x * (GB * HN * N1);
    const size_t TIR_OFF  = (size_t)BATCH * HN * N1;

    #pragma unroll 1
    for (int hf = 0; hf < 2; hf++) {
        float acc[2][4][4];
        #pragma unroll
        for (int rb = 0; rb < 2; rb++)
            #pragma unroll
            for (int nt = 0; nt < 4; nt++)
                { acc[rb][nt][0]=0.f; acc[rb][nt][1]=0.f; acc[rb][nt][2]=0.f; acc[rb][nt][3]=0.f; }

        #pragma unroll 2
        for (int kp = 0; kp < 8; kp++) {
            uint32_t a00[4], a01[4], a10[4], a11[4];
            ldsm4(a00, ha0 + kp * 64);
            ldsm4(a01, ha0 + kp * 64 + 32);
            ldsm4(a10, ha1 + kp * 64);
            ldsm4(a11, ha1 + kp * 64 + 32);
            #pragma unroll
            for (int nt = 0; nt < 4; nt++) {
                int ntile = hf * 32 + ng * 4 + nt;
                uint4 bh = __ldg(((const uint4*)g_W2s) + (ntile * 8 + kp) * 32 + lane);
                mma16816(acc[0][nt], a00, bh.x, bh.y);
                mma16816(acc[0][nt], a01, bh.z, bh.w);
                mma16816(acc[1][nt], a10, bh.x, bh.y);
                mma16816(acc[1][nt], a11, bh.z, bh.w);
            }
        }
        // epilogue: +bias, sigmoid, store o (overwrites dead xhi region)
        #pragma unroll
        for (int rb = 0; rb < 2; rb++) {
            int r0 = m0 + rb * 16 + (lane >> 2), r1 = r0 + 8;
            #pragma unroll
            for (int nt = 0; nt < 4; nt++) {
                int c = ng * 32 + nt * 8 + 2 * (lane & 3);
                float2 bb = *(const float2*)(b2s + hf * 256 + c);
                float2 v0 = make_float2(sigmoidf(acc[rb][nt][0] + bb.x),
                                        sigmoidf(acc[rb][nt][1] + bb.y));
                float2 v1 = make_float2(sigmoidf(acc[rb][nt][2] + bb.x),
                                        sigmoidf(acc[rb][nt][3] + bb.y));
                *(float2*)(osm + r0 * OSTRIDE_W + c) = v0;
                *(float2*)(osm + r1 * OSTRIDE_W + c) = v1;
            }
        }
        __syncthreads();

        // gather this half's outputs
        const size_t obase = (hf ? TIR_OFF : 0) + out_base;
        #pragma unroll
        for (int ii = 0; ii < (GB * HN * N1) / THREADS; ii++) {
            int e   = ii * THREADS + tid;
            int row = e / N1;              // 0..63
            int j   = e - row * N1;
            int g   = row >> 4;
            int c   = idx_s[g * N1 + j];
            out[obase + e] = osm[row * OSTRIDE_W + c];
        }
        __syncthreads();
    }
}

extern "C" void kernel_launch(void* const* d_in, const int* in_sizes, int n_in,
                              void* d_out, int out_size) {
    const float* rgb  = (const float*)d_in[0];
    const float* tir  = (const float*)d_in[1];
    const int*   gidx = (const int*)  d_in[2];
    const float* ln_g = (const float*)d_in[3];
    const float* ln_b = (const float*)d_in[4];
    const float* W1   = (const float*)d_in[5];
    const float* b1   = (const float*)d_in[6];
    const float* W2   = (const float*)d_in[7];
    const float* b2   = (const float*)d_in[8];

    prep_weights<<<512, 256>>>(W1, W2);

    cudaFuncSetAttribute(mlp_two_main,
                         cudaFuncAttributeMaxDynamicSharedMemorySize, SMEM_BYTES);
    mlp_two_main<<<BATCH / GB, THREADS, SMEM_BYTES>>>(
        rgb, tir, gidx, ln_g, ln_b, b1, b2, (float*)d_out);
}

// round 13
// speedup vs baseline: 1.2669x; 1.2669x over previous
#include <cuda_runtime.h>
#include <cuda_fp16.h>
#include <cstdint>

#define BATCH   4096
#define HN      16
#define N1      192
#define DIM     256
#define TWO_DIM 512
#define EPS     1e-5f
#define GB      4            // batches per CTA
#define THREADS 512

// ---- smem layout (bytes) ----
#define OFF_XHI  0           // xhi fp16 64x1040 = 66560 -> later o f32 (64x260x4)
#define OFF_H    66560       // h fp16 64x528 = 33792
#define OFF_IDX  100352      // 768 ints
#define OFF_B1   103424      // 256 f32
#define OFF_B2   104448      // 512 f32
#define OFF_LNG  106496      // 512 f32
#define OFF_LNB  108544      // 512 f32
#define SMEM_BYTES 110592

#define XSTRIDE_W 260        // u32 words per xhi row (256 data + 4 pad; ≡4 mod 32)
#define XSTRIDE_B 1040
#define HSTRIDE_W 132        // u32 words per h row (128 data + 4 pad)
#define HSTRIDE_B 528
#define OSTRIDE_W 260        // f32 words per o row (256 data + 4 pad)

// Pre-swizzled fp16 weights in B-fragment order. 256KB each.
__device__ __align__(16) __half g_W1s[131072];
__device__ __align__(16) __half g_W2s[131072];

__device__ __forceinline__ uint32_t smem_u32(const void* p) {
    return (uint32_t)__cvta_generic_to_shared(p);
}

__device__ __forceinline__ void ldsm4(uint32_t (&r)[4], uint32_t addr) {
    asm volatile("ldmatrix.sync.aligned.m8n8.x4.shared.b16 {%0,%1,%2,%3}, [%4];"
                 : "=r"(r[0]), "=r"(r[1]), "=r"(r[2]), "=r"(r[3]) : "r"(addr));
}

__device__ __forceinline__ void mma16816(float (&c)[4], const uint32_t (&a)[4],
                                         uint32_t b0, uint32_t b1) {
    asm volatile("mma.sync.aligned.m16n8k16.row.col.f32.f16.f16.f32 "
                 "{%0,%1,%2,%3}, {%4,%5,%6,%7}, {%8,%9}, {%0,%1,%2,%3};"
                 : "+f"(c[0]), "+f"(c[1]), "+f"(c[2]), "+f"(c[3])
                 : "r"(a[0]), "r"(a[1]), "r"(a[2]), "r"(a[3]), "r"(b0), "r"(b1));
}

__device__ __forceinline__ float sigmoidf(float x) {
    return 1.0f / (1.0f + __expf(-x));
}

// Swizzle both W1[256][512] and W2[512][256] into per-tile B-fragment order (fp16).
__global__ void prep_weights(const float* __restrict__ W1,
                             const float* __restrict__ W2) {
    int t = blockIdx.x * blockDim.x + threadIdx.x;   // [0, 131072)
    const float* W;
    __half2* dst;
    int kpairs, K;
    if (t < 65536) { W = W1; dst = (__half2*)g_W1s; kpairs = 16; K = 512; }
    else           { W = W2; dst = (__half2*)g_W2s; kpairs = 8;  K = 256; t -= 65536; }
    int j    = t & 3;
    int lane = (t >> 2) & 31;
    int rest = t >> 7;
    int kp    = rest % kpairs;
    int ntile = rest / kpairs;
    int n = ntile * 8 + (lane >> 2);
    int k = kp * 32 + (j >> 1) * 16 + (j & 1) * 8 + 2 * (lane & 3);
    dst[(((ntile * kpairs + kp) * 32 + lane) << 2) + j] =
        __floats2half2_rn(W[n * K + k], W[n * K + k + 1]);
}

__global__ __launch_bounds__(THREADS, 1)
void mlp_two_main(const float* __restrict__ rgb, const float* __restrict__ tir,
                  const int* __restrict__ gidx, const float* __restrict__ ln_g,
                  const float* __restrict__ ln_b, const float* __restrict__ b1,
                  const float* __restrict__ b2, float* __restrict__ out)
{
    extern __shared__ char smem[];
    uint32_t* xhi   = (uint32_t*)(smem + OFF_XHI);
    float*    osm   = (float*)(smem + OFF_XHI);
    uint32_t* hsm   = (uint32_t*)(smem + OFF_H);
    int*      idx_s = (int*)(smem + OFF_IDX);
    float*    b1s   = (float*)(smem + OFF_B1);
    float*    b2s   = (float*)(smem + OFF_B2);
    float*    lngs  = (float*)(smem + OFF_LNG);
    float*    lnbs  = (float*)(smem + OFF_LNB);

    const int tid  = threadIdx.x;
    const int lane = tid & 31;
    const int wid  = tid >> 5;

    // ---- preload idx / biases / LN params ----
    if (tid < 256) b1s[tid] = b1[tid];
    b2s[tid]  = b2[tid];
    lngs[tid] = ln_g[tid];
    lnbs[tid] = ln_b[tid];
    idx_s[tid] = gidx[blockIdx.x * (GB * N1) + tid];
    if (tid < GB * N1 - THREADS)
        idx_s[THREADS + tid] = gidx[blockIdx.x * (GB * N1) + THREADS + tid];
    __syncthreads();

    const float* rgb_cta = rgb + (size_t)blockIdx.x * (GB * HN * N1);
    const float* tir_cta = tir + (size_t)blockIdx.x * (GB * HN * N1);

    // ======== fused scatter + LayerNorm, direct fp16 write (4 rows/warp) ========
    #pragma unroll 1
    for (int rr = 0; rr < 4; rr++) {
        const int r = wid * 4 + rr;            // 0..63
        const int g = r >> 4;                  // local batch
        const float* rowr = rgb_cta + r * N1;
        const float* rowt = tir_cta + r * N1;
        float vr[6], vt[6];
        float s = 0.f, sq = 0.f;
        #pragma unroll
        for (int i = 0; i < 6; i++) {
            vr[i] = rowr[lane + 32 * i];
            vt[i] = rowt[lane + 32 * i];
            s  += vr[i] + vt[i];
            sq += vr[i] * vr[i] + vt[i] * vt[i];
        }
        #pragma unroll
        for (int o = 16; o > 0; o >>= 1) {
            s  += __shfl_xor_sync(~0u, s,  o);
            sq += __shfl_xor_sync(~0u, sq, o);
        }
        const float mu = s * (1.f / 512.f);
        const float rs = rsqrtf(sq * (1.f / 512.f) - mu * mu + EPS);
        const float nmr = -mu * rs;

        // fill whole row with zero-position LN value: b[k] - mu*rs*g[k]
        uint32_t* xrow = xhi + r * XSTRIDE_W;
        #pragma unroll
        for (int i = 0; i < 8; i++) {
            int kw = lane + 32 * i;            // word 0..255
            float2 g2 = *(const float2*)(lngs + 2 * kw);
            float2 bb = *(const float2*)(lnbs + 2 * kw);
            __half2 hv = __floats2half2_rn(fmaf(nmr, g2.x, bb.x),
                                           fmaf(nmr, g2.y, bb.y));
            xrow[kw] = *(uint32_t*)&hv;
        }
        __syncwarp();
        // scatter the 192 selected columns (rgb -> c, tir -> 256+c)
        __half* xrow_h = (__half*)xrow;
        #pragma unroll
        for (int i = 0; i < 6; i++) {
            int j = lane + 32 * i;
            int c = idx_s[g * N1 + j];
            float xv = (vr[i] - mu) * rs * lngs[c]       + lnbs[c];
            float tv = (vt[i] - mu) * rs * lngs[DIM + c] + lnbs[DIM + c];
            xrow_h[c]       = __float2half_rn(xv);
            xrow_h[DIM + c] = __float2half_rn(tv);
        }
    }
    __syncthreads();

    // ---- warp tile geometry: 2 mtiles (32 rows) x 8 ngroups (32 cols) ----
    const int mt = wid & 1, ng = wid >> 1;
    const int m0 = mt * 32;
    const int q  = lane >> 3, qr = lane & 7;
    const int arow16 = (q & 1) * 8 + qr;       // row within 16-block
    const uint32_t acol = (q >> 1) * 16;       // bytes
    const uint32_t xa0 = smem_u32(smem + OFF_XHI) + (m0 + arow16)      * XSTRIDE_B + acol;
    const uint32_t xa1 = smem_u32(smem + OFF_XHI) + (m0 + 16 + arow16) * XSTRIDE_B + acol;

    // ======== GEMM1: [64x512] @ W1^T -> h [64x256] fp16 ========
    {
        float acc[2][4][4];
        #pragma unroll
        for (int rb = 0; rb < 2; rb++)
            #pragma unroll
            for (int nt = 0; nt < 4; nt++)
                { acc[rb][nt][0]=0.f; acc[rb][nt][1]=0.f; acc[rb][nt][2]=0.f; acc[rb][nt][3]=0.f; }

        #pragma unroll 4
        for (int kp = 0; kp < 16; kp++) {
            uint32_t a00[4], a01[4], a10[4], a11[4];
            ldsm4(a00, xa0 + kp * 64);
            ldsm4(a01, xa0 + kp * 64 + 32);
            ldsm4(a10, xa1 + kp * 64);
            ldsm4(a11, xa1 + kp * 64 + 32);
            #pragma unroll
            for (int nt = 0; nt < 4; nt++) {
                int ntile = ng * 4 + nt;
                uint4 bh = __ldg(((const uint4*)g_W1s) + (ntile * 16 + kp) * 32 + lane);
                mma16816(acc[0][nt], a00, bh.x, bh.y);
                mma16816(acc[0][nt], a01, bh.z, bh.w);
                mma16816(acc[1][nt], a10, bh.x, bh.y);
                mma16816(acc[1][nt], a11, bh.z, bh.w);
            }
        }
        // epilogue: +bias, relu, fp16 round, store h
        #pragma unroll
        for (int rb = 0; rb < 2; rb++) {
            int r0 = m0 + rb * 16 + (lane >> 2), r1 = r0 + 8;
            #pragma unroll
            for (int nt = 0; nt < 4; nt++) {
                int cn = ng * 32 + nt * 8 + 2 * (lane & 3);
                int cw = cn >> 1;
                float2 bb = *(const float2*)(b1s + cn);
                __half2 h0 = __floats2half2_rn(fmaxf(acc[rb][nt][0] + bb.x, 0.f),
                                               fmaxf(acc[rb][nt][1] + bb.y, 0.f));
                __half2 h1 = __floats2half2_rn(fmaxf(acc[rb][nt][2] + bb.x, 0.f),
                                               fmaxf(acc[rb][nt][3] + bb.y, 0.f));
                hsm[r0 * HSTRIDE_W + cw] = *(uint32_t*)&h0;
                hsm[r1 * HSTRIDE_W + cw] = *(uint32_t*)&h1;
            }
        }
    }
    __syncthreads();

    // ======== GEMM2 (two 256-col halves) + sigmoid + gather ========
    const uint32_t ha0 = smem_u32(smem + OFF_H) + (m0 + arow16)      * HSTRIDE_B + acol;
    const uint32_t ha1 = smem_u32(smem + OFF_H) + (m0 + 16 + arow16) * HSTRIDE_B + acol;
    const size_t out_base = (size_t)blockIdx.x * (GB * HN * N1);
    const size_t TIR_OFF  = (size_t)BATCH * HN * N1;

    #pragma unroll 1
    for (int hf = 0; hf < 2; hf++) {
        float acc[2][4][4];
        #pragma unroll
        for (int rb = 0; rb < 2; rb++)
            #pragma unroll
            for (int nt = 0; nt < 4; nt++)
                { acc[rb][nt][0]=0.f; acc[rb][nt][1]=0.f; acc[rb][nt][2]=0.f; acc[rb][nt][3]=0.f; }

        #pragma unroll 4
        for (int kp = 0; kp < 8; kp++) {
            uint32_t a00[4], a01[4], a10[4], a11[4];
            ldsm4(a00, ha0 + kp * 64);
            ldsm4(a01, ha0 + kp * 64 + 32);
            ldsm4(a10, ha1 + kp * 64);
            ldsm4(a11, ha1 + kp * 64 + 32);
            #pragma unroll
            for (int nt = 0; nt < 4; nt++) {
                int ntile = hf * 32 + ng * 4 + nt;
                uint4 bh = __ldg(((const uint4*)g_W2s) + (ntile * 8 + kp) * 32 + lane);
                mma16816(acc[0][nt], a00, bh.x, bh.y);
                mma16816(acc[0][nt], a01, bh.z, bh.w);
                mma16816(acc[1][nt], a10, bh.x, bh.y);
                mma16816(acc[1][nt], a11, bh.z, bh.w);
            }
        }
        // epilogue: +bias, sigmoid, store o (overwrites dead xhi region)
        #pragma unroll
        for (int rb = 0; rb < 2; rb++) {
            int r0 = m0 + rb * 16 + (lane >> 2), r1 = r0 + 8;
            #pragma unroll
            for (int nt = 0; nt < 4; nt++) {
                int c = ng * 32 + nt * 8 + 2 * (lane & 3);
                float2 bb = *(const float2*)(b2s + hf * 256 + c);
                float2 v0 = make_float2(sigmoidf(acc[rb][nt][0] + bb.x),
                                        sigmoidf(acc[rb][nt][1] + bb.y));
                float2 v1 = make_float2(sigmoidf(acc[rb][nt][2] + bb.x),
                                        sigmoidf(acc[rb][nt][3] + bb.y));
                *(float2*)(osm + r0 * OSTRIDE_W + c) = v0;
                *(float2*)(osm + r1 * OSTRIDE_W + c) = v1;
            }
        }
        __syncthreads();

        // gather this half's outputs
        const size_t obase = (hf ? TIR_OFF : 0) + out_base;
        #pragma unroll
        for (int ii = 0; ii < (GB * HN * N1) / THREADS; ii++) {
            int e   = ii * THREADS + tid;
            int row = e / N1;              // 0..63
            int j   = e - row * N1;
            int g   = row >> 4;
            int c   = idx_s[g * N1 + j];
            out[obase + e] = osm[row * OSTRIDE_W + c];
        }
        __syncthreads();
    }
}

extern "C" void kernel_launch(void* const* d_in, const int* in_sizes, int n_in,
                              void* d_out, int out_size) {
    const float* rgb  = (const float*)d_in[0];
    const float* tir  = (const float*)d_in[1];
    const int*   gidx = (const int*)  d_in[2];
    const float* ln_g = (const float*)d_in[3];
    const float* ln_b = (const float*)d_in[4];
    const float* W1   = (const float*)d_in[5];
    const float* b1   = (const float*)d_in[6];
    const float* W2   = (const float*)d_in[7];
    const float* b2   = (const float*)d_in[8];

    prep_weights<<<512, 256>>>(W1, W2);

    cudaFuncSetAttribute(mlp_two_main,
                         cudaFuncAttributeMaxDynamicSharedMemorySize, SMEM_BYTES);
    mlp_two_main<<<BATCH / GB, THREADS, SMEM_BYTES>>>(
        rgb, tir, gidx, ln_g, ln_b, b1, b2, (float*)d_out);
}

// round 17
// speedup vs baseline: 1.3586x; 1.0724x over previous
#include <cuda_runtime.h>
#include <cuda_fp16.h>
#include <cstdint>

#define BATCH   4096
#define HN      16
#define N1      192
#define DIM     256
#define TWO_DIM 512
#define EPS     1e-5f
#define GB      2            // batches per CTA -> M = 32 rows
#define THREADS 256

// ---- smem layout (bytes) ----
#define OFF_XHI  0           // x fp16 32 x 1040B = 33280 -> later o f32 (32 x 260 x 4)
#define OFF_H    33280       // h fp16 32 x 528 = 16896
#define OFF_IDX  50176       // 384 ints = 1536
#define OFF_B1   51712       // 256 f32
#define OFF_B2   52736       // 512 f32
#define OFF_LNG  54784       // 512 f32
#define OFF_LNB  56832       // 512 f32
#define SMEM_BYTES 58880

#define XSTRIDE_W 260        // u32 words per x row (1040B = 65*16, ldsm-aligned)
#define XSTRIDE_B 1040
#define HSTRIDE_W 132        // u32 words per h row (528B = 33*16, ldsm-aligned)
#define HSTRIDE_B 528
#define OSTRIDE_W 260        // f32 words per o row (even -> aligned float2 stores)

// Pre-swizzled fp16 weights in B-fragment order. 256KB each.
__device__ __align__(16) __half g_W1s[131072];
__device__ __align__(16) __half g_W2s[131072];

__device__ __forceinline__ uint32_t smem_u32(const void* p) {
    return (uint32_t)__cvta_generic_to_shared(p);
}

__device__ __forceinline__ void ldsm4(uint32_t (&r)[4], uint32_t addr) {
    asm volatile("ldmatrix.sync.aligned.m8n8.x4.shared.b16 {%0,%1,%2,%3}, [%4];"
                 : "=r"(r[0]), "=r"(r[1]), "=r"(r[2]), "=r"(r[3]) : "r"(addr));
}

__device__ __forceinline__ void mma16816(float (&c)[4], const uint32_t (&a)[4],
                                         uint32_t b0, uint32_t b1) {
    asm volatile("mma.sync.aligned.m16n8k16.row.col.f32.f16.f16.f32 "
                 "{%0,%1,%2,%3}, {%4,%5,%6,%7}, {%8,%9}, {%0,%1,%2,%3};"
                 : "+f"(c[0]), "+f"(c[1]), "+f"(c[2]), "+f"(c[3])
                 : "r"(a[0]), "r"(a[1]), "r"(a[2]), "r"(a[3]), "r"(b0), "r"(b1));
}

__device__ __forceinline__ float sigmoidf(float x) {
    return 1.0f / (1.0f + __expf(-x));
}

// Swizzle both W1[256][512] and W2[512][256] into per-tile B-fragment order (fp16).
__global__ void prep_weights(const float* __restrict__ W1,
                             const float* __restrict__ W2) {
    int t = blockIdx.x * blockDim.x + threadIdx.x;   // [0, 131072)
    const float* W;
    __half2* dst;
    int kpairs, K;
    if (t < 65536) { W = W1; dst = (__half2*)g_W1s; kpairs = 16; K = 512; }
    else           { W = W2; dst = (__half2*)g_W2s; kpairs = 8;  K = 256; t -= 65536; }
    int j    = t & 3;
    int lane = (t >> 2) & 31;
    int rest = t >> 7;
    int kp    = rest % kpairs;
    int ntile = rest / kpairs;
    int n = ntile * 8 + (lane >> 2);
    int k = kp * 32 + (j >> 1) * 16 + (j & 1) * 8 + 2 * (lane & 3);
    dst[(((ntile * kpairs + kp) * 32 + lane) << 2) + j] =
        __floats2half2_rn(W[n * K + k], W[n * K + k + 1]);
}

__global__ __launch_bounds__(THREADS, 2)
void mlp_two_main(const float* __restrict__ rgb, const float* __restrict__ tir,
                  const int* __restrict__ gidx, const float* __restrict__ ln_g,
                  const float* __restrict__ ln_b, const float* __restrict__ b1,
                  const float* __restrict__ b2, float* __restrict__ out)
{
    extern __shared__ char smem[];
    uint32_t* xhi   = (uint32_t*)(smem + OFF_XHI);
    float*    osm   = (float*)(smem + OFF_XHI);
    uint32_t* hsm   = (uint32_t*)(smem + OFF_H);
    int*      idx_s = (int*)(smem + OFF_IDX);
    float*    b1s   = (float*)(smem + OFF_B1);
    float*    b2s   = (float*)(smem + OFF_B2);
    float*    lngs  = (float*)(smem + OFF_LNG);
    float*    lnbs  = (float*)(smem + OFF_LNB);

    const int tid  = threadIdx.x;
    const int lane = tid & 31;
    const int wid  = tid >> 5;

    // ---- preload idx / biases / LN params (256 threads) ----
    b1s[tid] = b1[tid];
    b2s[tid]         = b2[tid];
    b2s[256 + tid]   = b2[256 + tid];
    lngs[tid]        = ln_g[tid];
    lngs[256 + tid]  = ln_g[256 + tid];
    lnbs[tid]        = ln_b[tid];
    lnbs[256 + tid]  = ln_b[256 + tid];
    idx_s[tid] = gidx[blockIdx.x * (GB * N1) + tid];
    if (tid < GB * N1 - THREADS)
        idx_s[THREADS + tid] = gidx[blockIdx.x * (GB * N1) + THREADS + tid];
    __syncthreads();

    const float* rgb_cta = rgb + (size_t)blockIdx.x * (GB * HN * N1);
    const float* tir_cta = tir + (size_t)blockIdx.x * (GB * HN * N1);

    // ======== fused scatter + LayerNorm, direct fp16 write (4 rows/warp) ========
    #pragma unroll 1
    for (int rr = 0; rr < 4; rr++) {
        const int r = wid * 4 + rr;            // 0..31
        const int g = r >> 4;                  // local batch
        const float* rowr = rgb_cta + r * N1;
        const float* rowt = tir_cta + r * N1;
        float vr[6], vt[6];
        float s = 0.f, sq = 0.f;
        #pragma unroll
        for (int i = 0; i < 6; i++) {
            vr[i] = rowr[lane + 32 * i];
            vt[i] = rowt[lane + 32 * i];
            s  += vr[i] + vt[i];
            sq += vr[i] * vr[i] + vt[i] * vt[i];
        }
        #pragma unroll
        for (int o = 16; o > 0; o >>= 1) {
            s  += __shfl_xor_sync(~0u, s,  o);
            sq += __shfl_xor_sync(~0u, sq, o);
        }
        const float mu = s * (1.f / 512.f);
        const float rs = rsqrtf(sq * (1.f / 512.f) - mu * mu + EPS);
        const float nmr = -mu * rs;

        // fill whole row with zero-position LN value: b[k] - mu*rs*g[k]
        uint32_t* xrow = xhi + r * XSTRIDE_W;
        #pragma unroll
        for (int i = 0; i < 8; i++) {
            int kw = lane + 32 * i;            // word 0..255
            float2 g2 = *(const float2*)(lngs + 2 * kw);
            float2 bb = *(const float2*)(lnbs + 2 * kw);
            __half2 hv = __floats2half2_rn(fmaf(nmr, g2.x, bb.x),
                                           fmaf(nmr, g2.y, bb.y));
            xrow[kw] = *(uint32_t*)&hv;
        }
        __syncwarp();
        // scatter the 192 selected columns (rgb -> c, tir -> 256+c)
        __half* xrow_h = (__half*)xrow;
        #pragma unroll
        for (int i = 0; i < 6; i++) {
            int j = lane + 32 * i;
            int c = idx_s[g * N1 + j];
            float xv = (vr[i] - mu) * rs * lngs[c]       + lnbs[c];
            float tv = (vt[i] - mu) * rs * lngs[DIM + c] + lnbs[DIM + c];
            xrow_h[c]       = __float2half_rn(xv);
            xrow_h[DIM + c] = __float2half_rn(tv);
        }
    }
    __syncthreads();

    // ---- warp tile geometry: 1 mtile (32 rows) x 8 ngroups (32 cols each) ----
    const int ng = wid;                        // 0..7
    const int q  = lane >> 3, qr = lane & 7;
    const int arow16 = (q & 1) * 8 + qr;       // row within 16-block
    const uint32_t acol = (q >> 1) * 16;       // bytes
    const uint32_t xa0 = smem_u32(smem + OFF_XHI) + (arow16)      * XSTRIDE_B + acol;
    const uint32_t xa1 = smem_u32(smem + OFF_XHI) + (16 + arow16) * XSTRIDE_B + acol;

    // ======== GEMM1: [32x512] @ W1^T -> h [32x256] fp16 ========
    {
        float acc[2][4][4];
        #pragma unroll
        for (int rb = 0; rb < 2; rb++)
            #pragma unroll
            for (int nt = 0; nt < 4; nt++)
                { acc[rb][nt][0]=0.f; acc[rb][nt][1]=0.f; acc[rb][nt][2]=0.f; acc[rb][nt][3]=0.f; }

        #pragma unroll 4
        for (int kp = 0; kp < 16; kp++) {
            uint32_t a00[4], a01[4], a10[4], a11[4];
            ldsm4(a00, xa0 + kp * 64);
            ldsm4(a01, xa0 + kp * 64 + 32);
            ldsm4(a10, xa1 + kp * 64);
            ldsm4(a11, xa1 + kp * 64 + 32);
            #pragma unroll
            for (int nt = 0; nt < 4; nt++) {
                int ntile = ng * 4 + nt;
                uint4 bh = __ldg(((const uint4*)g_W1s) + (ntile * 16 + kp) * 32 + lane);
                mma16816(acc[0][nt], a00, bh.x, bh.y);
                mma16816(acc[0][nt], a01, bh.z, bh.w);
                mma16816(acc[1][nt], a10, bh.x, bh.y);
                mma16816(acc[1][nt], a11, bh.z, bh.w);
            }
        }
        // epilogue: +bias, relu, fp16 round, store h
        #pragma unroll
        for (int rb = 0; rb < 2; rb++) {
            int r0 = rb * 16 + (lane >> 2), r1 = r0 + 8;
            #pragma unroll
            for (int nt = 0; nt < 4; nt++) {
                int cn = ng * 32 + nt * 8 + 2 * (lane & 3);
                int cw = cn >> 1;
                float2 bb = *(const float2*)(b1s + cn);
                __half2 h0 = __floats2half2_rn(fmaxf(acc[rb][nt][0] + bb.x, 0.f),
                                               fmaxf(acc[rb][nt][1] + bb.y, 0.f));
                __half2 h1 = __floats2half2_rn(fmaxf(acc[rb][nt][2] + bb.x, 0.f),
                                               fmaxf(acc[rb][nt][3] + bb.y, 0.f));
                hsm[r0 * HSTRIDE_W + cw] = *(uint32_t*)&h0;
                hsm[r1 * HSTRIDE_W + cw] = *(uint32_t*)&h1;
            }
        }
    }
    __syncthreads();

    // ======== GEMM2 (two 256-col halves) + sigmoid + gather ========
    const uint32_t ha0 = smem_u32(smem + OFF_H) + (arow16)      * HSTRIDE_B + acol;
    const uint32_t ha1 = smem_u32(smem + OFF_H) + (16 + arow16) * HSTRIDE_B + acol;
    const size_t out_base = (size_t)blockIdx.x * (GB * HN * N1);
    const size_t TIR_OFF  = (size_t)BATCH * HN * N1;

    #pragma unroll 1
    for (int hf = 0; hf < 2; hf++) {
        float acc[2][4][4];
        #pragma unroll
        for (int rb = 0; rb < 2; rb++)
            #pragma unroll
            for (int nt = 0; nt < 4; nt++)
                { acc[rb][nt][0]=0.f; acc[rb][nt][1]=0.f; acc[rb][nt][2]=0.f; acc[rb][nt][3]=0.f; }

        #pragma unroll 4
        for (int kp = 0; kp < 8; kp++) {
            uint32_t a00[4], a01[4], a10[4], a11[4];
            ldsm4(a00, ha0 + kp * 64);
            ldsm4(a01, ha0 + kp * 64 + 32);
            ldsm4(a10, ha1 + kp * 64);
            ldsm4(a11, ha1 + kp * 64 + 32);
            #pragma unroll
            for (int nt = 0; nt < 4; nt++) {
                int ntile = hf * 32 + ng * 4 + nt;
                uint4 bh = __ldg(((const uint4*)g_W2s) + (ntile * 8 + kp) * 32 + lane);
                mma16816(acc[0][nt], a00, bh.x, bh.y);
                mma16816(acc[0][nt], a01, bh.z, bh.w);
                mma16816(acc[1][nt], a10, bh.x, bh.y);
                mma16816(acc[1][nt], a11, bh.z, bh.w);
            }
        }
        // epilogue: +bias, sigmoid, store o (overwrites dead xhi region)
        #pragma unroll
        for (int rb = 0; rb < 2; rb++) {
            int r0 = rb * 16 + (lane >> 2), r1 = r0 + 8;
            #pragma unroll
            for (int nt = 0; nt < 4; nt++) {
                int c = ng * 32 + nt * 8 + 2 * (lane & 3);
                float2 bb = *(const float2*)(b2s + hf * 256 + c);
                float2 v0 = make_float2(sigmoidf(acc[rb][nt][0] + bb.x),
                                        sigmoidf(acc[rb][nt][1] + bb.y));
                float2 v1 = make_float2(sigmoidf(acc[rb][nt][2] + bb.x),
                                        sigmoidf(acc[rb][nt][3] + bb.y));
                *(float2*)(osm + r0 * OSTRIDE_W + c) = v0;
                *(float2*)(osm + r1 * OSTRIDE_W + c) = v1;
            }
        }
        __syncthreads();

        // gather this half's outputs (vectorized: 4 consecutive j per thread)
        const size_t obase = (hf ? TIR_OFF : 0) + out_base;
        #pragma unroll
        for (int ii = 0; ii < (GB * HN * N1 / 4) / THREADS; ii++) {
            int e4  = ii * THREADS + tid;       // float4 index
            int e   = e4 * 4;
            int row = e / N1;                   // 0..31 (4-groups never cross rows)
            int j   = e - row * N1;
            int g   = row >> 4;
            const int* ij = idx_s + g * N1 + j;
            const float* orow = osm + row * OSTRIDE_W;
            float4 v = make_float4(orow[ij[0]], orow[ij[1]], orow[ij[2]], orow[ij[3]]);
            *(float4*)(out + obase + e) = v;
        }
        __syncthreads();
    }
}

extern "C" void kernel_launch(void* const* d_in, const int* in_sizes, int n_in,
                              void* d_out, int out_size) {
    const float* rgb  = (const float*)d_in[0];
    const float* tir  = (const float*)d_in[1];
    const int*   gidx = (const int*)  d_in[2];
    const float* ln_g = (const float*)d_in[3];
    const float* ln_b = (const float*)d_in[4];
    const float* W1   = (const float*)d_in[5];
    const float* b1   = (const float*)d_in[6];
    const float* W2   = (const float*)d_in[7];
    const float* b2   = (const float*)d_in[8];

    prep_weights<<<512, 256>>>(W1, W2);

    cudaFuncSetAttribute(mlp_two_main,
                         cudaFuncAttributeMaxDynamicSharedMemorySize, SMEM_BYTES);
    mlp_two_main<<<BATCH / GB, THREADS, SMEM_BYTES>>>(
        rgb, tir, gidx, ln_g, ln_b, b1, b2, (float*)d_out);
}